// round 6
// baseline (speedup 1.0000x reference)
#include <cuda_runtime.h>

// Tree shape: DEPTH=4, V=4.  n4=1, n3=5, n2=25, n1=125, n0=125.
#define NV   4
#define N1   125
#define N2   25
#define N3   5
#define NTHREADS 64   // 2 batch elements per thread -> 128 elems/block

typedef unsigned long long ull;

__device__ __forceinline__ float ex2f(float a) {
    float r;
    asm("ex2.approx.f32 %0, %1;" : "=f"(r) : "f"(a));
    return r;
}
__device__ __forceinline__ float lg2f(float a) {
    float r;
    asm("lg2.approx.f32 %0, %1;" : "=f"(r) : "f"(a));
    return r;
}

// ---- packed fp32x2 ops (Blackwell FFMA2 pipe; 2 FMAs per issue slot) ----
__device__ __forceinline__ ull fma2(ull a, ull b, ull c) {
    ull r;
    asm("fma.rn.f32x2 %0, %1, %2, %3;" : "=l"(r) : "l"(a), "l"(b), "l"(c));
    return r;
}
__device__ __forceinline__ ull mul2(ull a, ull b) {
    ull r;
    asm("mul.rn.f32x2 %0, %1, %2;" : "=l"(r) : "l"(a), "l"(b));
    return r;
}
__device__ __forceinline__ ull add2(ull a, ull b) {
    ull r;
    asm("add.rn.f32x2 %0, %1, %2;" : "=l"(r) : "l"(a), "l"(b));
    return r;
}
__device__ __forceinline__ ull pack2(float x, float y) {
    ull r;
    asm("mov.b64 %0, {%1, %2};" : "=l"(r) : "f"(x), "f"(y));
    return r;
}
__device__ __forceinline__ void unpack2(ull a, float& x, float& y) {
    asm("mov.b64 {%0, %1}, %2;" : "=f"(x), "=f"(y) : "l"(a));
}

// Poly constants (degree-5 Taylor of 2^f on f in [-0.5, 0.5]; rel err <= 3.5e-6)
#define MAG2  0x4B4000004B400000ULL   // (12582912.0f, 12582912.0f)
#define NMAG2 0xCB400000CB400000ULL   // (-12582912.0f, -12582912.0f)
#define NONE2 0xBF800000BF800000ULL   // (-1.0f, -1.0f)

struct P2C { ull c5, c4, c3, c2, c1, c0; };

// Level-1 node m, two batch elements (A,B).
// sA[m] = (lam_m0, pow_m0, lam_m1, pow_m1)
// sB[m] = (lam_m2, pow_m2, lam0_m, lam_m3)
// sC[m] = packed (pow_m3, pow_m3)
// Vars 0..2 via MUFU ex2; var 3 via packed f32x2 polynomial 2^t.
__device__ __forceinline__ void eval_f1(
    int m,
    const float4* __restrict__ sA, const float4* __restrict__ sB,
    const ull* __restrict__ sC,
    float lxA0, float lxA1, float lxA2,
    float lxB0, float lxB1, float lxB2,
    ull lx3p, const P2C& C,
    float& fA, float& fB)
{
    const float4 qa = sA[m];
    const float4 qb = sB[m];
    const ull    pw = sC[m];

    // MUFU path: 6 independent EX2s in flight
    const float eA0 = ex2f(qa.y * lxA0);
    const float eB0 = ex2f(qa.y * lxB0);
    const float eA1 = ex2f(qa.w * lxA1);
    const float eB1 = ex2f(qa.w * lxB1);
    const float eA2 = ex2f(qb.y * lxA2);
    const float eB2 = ex2f(qb.y * lxB2);

    // Poly path (var 3), fully packed: t = pow3 * lg2(x3) for both elems
    const ull t  = mul2(pw, lx3p);
    const ull r  = add2(t, MAG2);        // t + magic -> round-to-int in mantissa
    const ull nf = add2(r, NMAG2);       // nf = round(t)
    const ull f  = fma2(nf, NONE2, t);   // f = t - nf, f in [-0.5, 0.5]
    ull p = fma2(C.c5, f, C.c4);
    p = fma2(p, f, C.c3);
    p = fma2(p, f, C.c2);
    p = fma2(p, f, C.c1);
    p = fma2(p, f, C.c0);
    float rA, rB;
    unpack2(r, rA, rB);
    // 2^n from the magic-rounded bits: bits(r) = 0x4B400000 + n
    const float tnA = __int_as_float((__float_as_int(rA) << 23) + 0x3F800000);
    const float tnB = __int_as_float((__float_as_int(rB) << 23) + 0x3F800000);
    const ull v = mul2(p, pack2(tnA, tnB));
    float vA, vB;
    unpack2(v, vA, vB);

    fA = fmaf(qb.w, vA, fmaf(qa.x, eA0, fmaf(qa.z, eA1, fmaf(qb.x, eA2, qb.z))));
    fB = fmaf(qb.w, vB, fmaf(qa.x, eB0, fmaf(qa.z, eB1, fmaf(qb.x, eB2, qb.z))));
}

__global__ __launch_bounds__(NTHREADS)
void nested_formula_kernel(const float4* __restrict__ x,      // (B, 4) as float4
                           const float*  __restrict__ lam0,   // (125,)
                           const float*  __restrict__ lam1,   // (125,4)
                           const float*  __restrict__ pow1,
                           const float*  __restrict__ lam2,   // (25,4)
                           const float*  __restrict__ pow2,
                           const float*  __restrict__ lam3,   // (5,4)
                           const float*  __restrict__ pow3,
                           const float*  __restrict__ lam4,   // (1,4)
                           const float*  __restrict__ pow4,
                           float* __restrict__ out,           // (B,)
                           int B) {
    __shared__ __align__(16) float4 sA[N1];        // 2000 B
    __shared__ __align__(16) float4 sB[N1];        // 2000 B
    __shared__ __align__(16) ull    sC[N1];        // 1000 B
    __shared__ __align__(16) float2 s2[N2 * NV];   //  800 B
    __shared__ __align__(16) float2 s3[N3 * NV];   //  160 B
    __shared__ __align__(16) float2 s4[NV];        //   32 B

    const int tid = threadIdx.x;
    for (int m = tid; m < N1; m += NTHREADS) {
        sA[m] = make_float4(lam1[4*m+0], pow1[4*m+0], lam1[4*m+1], pow1[4*m+1]);
        sB[m] = make_float4(lam1[4*m+2], pow1[4*m+2], lam0[m],     lam1[4*m+3]);
        const float pw3 = pow1[4*m+3];
        sC[m] = pack2(pw3, pw3);
    }
    for (int i = tid; i < N2 * NV; i += NTHREADS)
        s2[i] = make_float2(lam2[i], pow2[i]);
    if (tid < N3 * NV) s3[tid] = make_float2(lam3[tid], pow3[tid]);
    if (tid < NV)      s4[tid] = make_float2(lam4[tid], pow4[tid]);
    __syncthreads();

    const float4* v2 = (const float4*)s2;

    // Two batch elements per thread, coalesced within the block.
    const int b0 = blockIdx.x * (2 * NTHREADS) + tid;
    const int b1 = b0 + NTHREADS;

    const float4 xA = x[b0];
    const float4 xB = x[b1];
    const float lxA[4] = {lg2f(xA.x), lg2f(xA.y), lg2f(xA.z), lg2f(xA.w)};
    const float lxB[4] = {lg2f(xB.x), lg2f(xB.y), lg2f(xB.z), lg2f(xB.w)};
    const ull lx3p = pack2(lxA[3], lxB[3]);

    P2C C;
    C.c5 = pack2(1.3333558e-3f,  1.3333558e-3f);
    C.c4 = pack2(9.6181291e-3f,  9.6181291e-3f);
    C.c3 = pack2(5.5504109e-2f,  5.5504109e-2f);
    C.c2 = pack2(2.4022651e-1f,  2.4022651e-1f);
    C.c1 = pack2(6.9314718e-1f,  6.9314718e-1f);
    C.c0 = pack2(1.0f,           1.0f);

    float acc4A = 0.0f, acc4B = 0.0f;
    #pragma unroll 1
    for (int j = 0; j < 5; ++j) {          // 5 level-3 nodes (root's children)
        float acc3A = 0.0f, acc3B = 0.0f;
        #pragma unroll
        for (int kk = 0; kk < 5; ++kk) {   // 5 level-2 children of node j (unrolled)
            const int k = j * 5 + kk;
            float acc2A, acc2B;
            eval_f1(k * 5 + 4, sA, sB, sC,
                    lxA[0], lxA[1], lxA[2], lxB[0], lxB[1], lxB[2],
                    lx3p, C, acc2A, acc2B);
            const float4 p0 = v2[2 * k];       // (lam_k0,pow_k0,lam_k1,pow_k1)
            const float4 p1 = v2[2 * k + 1];   // (lam_k2,pow_k2,lam_k3,pow_k3)
            #pragma unroll
            for (int mm = 0; mm < 4; ++mm) {
                float fA, fB;
                eval_f1(k * 5 + mm, sA, sB, sC,
                        lxA[0], lxA[1], lxA[2], lxB[0], lxB[1], lxB[2],
                        lx3p, C, fA, fB);
                const float lam = (mm == 0) ? p0.x : (mm == 1) ? p0.z : (mm == 2) ? p1.x : p1.z;
                const float pw  = (mm == 0) ? p0.y : (mm == 1) ? p0.w : (mm == 2) ? p1.y : p1.w;
                acc2A = fmaf(lam * ex2f(pw * lxA[mm]), fA, acc2A);
                acc2B = fmaf(lam * ex2f(pw * lxB[mm]), fB, acc2B);
            }
            if (kk < 4) {
                const float2 lp = s3[j * 4 + kk];
                acc3A = fmaf(lp.x * ex2f(lp.y * lxA[kk]), acc2A, acc3A);
                acc3B = fmaf(lp.x * ex2f(lp.y * lxB[kk]), acc2B, acc3B);
            } else {
                acc3A += acc2A;
                acc3B += acc2B;
            }
        }
        if (j < 4) {
            const float lxjA = (j == 0) ? lxA[0] : (j == 1) ? lxA[1] : (j == 2) ? lxA[2] : lxA[3];
            const float lxjB = (j == 0) ? lxB[0] : (j == 1) ? lxB[1] : (j == 2) ? lxB[2] : lxB[3];
            const float2 lp = s4[j];
            acc4A = fmaf(lp.x * ex2f(lp.y * lxjA), acc3A, acc4A);
            acc4B = fmaf(lp.x * ex2f(lp.y * lxjB), acc3B, acc4B);
        } else {
            acc4A += acc3A;
            acc4B += acc3B;
        }
    }

    out[b0] = acc4A;
    out[b1] = acc4B;
}

extern "C" void kernel_launch(void* const* d_in, const int* in_sizes, int n_in,
                              void* d_out, int out_size) {
    // metadata order: x, lam0, lam1, pow1, lam2, pow2, lam3, pow3, lam4, pow4
    const float4* x    = (const float4*)d_in[0];
    const float*  lam0 = (const float*)d_in[1];
    const float*  lam1 = (const float*)d_in[2];
    const float*  pow1 = (const float*)d_in[3];
    const float*  lam2 = (const float*)d_in[4];
    const float*  pow2 = (const float*)d_in[5];
    const float*  lam3 = (const float*)d_in[6];
    const float*  pow3 = (const float*)d_in[7];
    const float*  lam4 = (const float*)d_in[8];
    const float*  pow4 = (const float*)d_in[9];
    float* out = (float*)d_out;

    const int B = in_sizes[0] / 4;                 // x has B*4 elements
    const int elemsPerBlock = 2 * NTHREADS;        // 128
    const int grid = (B + elemsPerBlock - 1) / elemsPerBlock;
    nested_formula_kernel<<<grid, NTHREADS>>>(x, lam0, lam1, pow1, lam2, pow2,
                                              lam3, pow3, lam4, pow4, out, B);
}

// round 8
// speedup vs baseline: 1.0767x; 1.0767x over previous
#include <cuda_runtime.h>

// Tree shape: DEPTH=4, V=4.  n4=1, n3=5, n2=25, n1=125, n0=125.
#define NV   4
#define N1   125
#define N2   25
#define N3   5
#define NTHREADS 64   // 2 batch elements per thread -> 128 elems/block

typedef unsigned long long ull;

__device__ __forceinline__ float ex2f(float a) {
    float r;
    asm("ex2.approx.f32 %0, %1;" : "=f"(r) : "f"(a));
    return r;
}
__device__ __forceinline__ float lg2f(float a) {
    float r;
    asm("lg2.approx.f32 %0, %1;" : "=f"(r) : "f"(a));
    return r;
}

// ---- packed fp32x2 ops (Blackwell packed-FMA pipe; 2 FMAs per issue slot) ----
__device__ __forceinline__ ull fma2(ull a, ull b, ull c) {
    ull r;
    asm("fma.rn.f32x2 %0, %1, %2, %3;" : "=l"(r) : "l"(a), "l"(b), "l"(c));
    return r;
}
__device__ __forceinline__ ull mul2(ull a, ull b) {
    ull r;
    asm("mul.rn.f32x2 %0, %1, %2;" : "=l"(r) : "l"(a), "l"(b));
    return r;
}
__device__ __forceinline__ ull add2(ull a, ull b) {
    ull r;
    asm("add.rn.f32x2 %0, %1, %2;" : "=l"(r) : "l"(a), "l"(b));
    return r;
}
__device__ __forceinline__ ull pack2(float x, float y) {
    ull r;
    asm("mov.b64 %0, {%1, %2};" : "=l"(r) : "f"(x), "f"(y));
    return r;
}
__device__ __forceinline__ void unpack2(ull a, float& x, float& y) {
    asm("mov.b64 {%0, %1}, %2;" : "=f"(x), "=f"(y) : "l"(a));
}

// Magic rounding constants (round-to-nearest-int via mantissa shift)
#define MAG2  0x4B4000004B400000ULL   // ( 12582912.0f,  12582912.0f)
#define NMAG2 0xCB400000CB400000ULL   // (-12582912.0f, -12582912.0f)
#define NONE2 0xBF800000BF800000ULL   // (-1.0f, -1.0f)

struct P2C { ull c4, c3, c2, c1, c0; };

// Packed 2^t for two lanes; exponent folded via integer add into bits(p).
// bits(r) = 0x4B400000 + n  =>  bits(r)<<23 == n<<23 (mod 2^32).
__device__ __forceinline__ void exp2_pair(ull t, const P2C& C, float& vA, float& vB) {
    const ull r  = add2(t, MAG2);
    const ull nf = add2(r, NMAG2);       // nf = round(t)
    const ull f  = fma2(nf, NONE2, t);   // f = t - nf, f in [-0.5, 0.5]
    ull p = fma2(C.c4, f, C.c3);
    p = fma2(p, f, C.c2);
    p = fma2(p, f, C.c1);
    p = fma2(p, f, C.c0);
    float pA, pB, rA, rB;
    unpack2(p, pA, pB);                  // free (register aliasing)
    unpack2(r, rA, rB);
    vA = __int_as_float(__float_as_int(pA) + (__float_as_int(rA) << 23));
    vB = __int_as_float(__float_as_int(pB) + (__float_as_int(rB) << 23));
}

// Level-1 node m, two batch elements (A,B).
// sA[m] = (lam_m0, pow_m0, lam_m1, pow_m1)
// sB[m] = (lam_m2, pow_m2, lam0_m, lam_m3)
// sC[m] = packed (pow_m3, pow_m3)
// Vars 0..2 via MUFU ex2; var 3 via packed f32x2 polynomial 2^t.
__device__ __forceinline__ void eval_f1(
    int m,
    const float4* __restrict__ sA, const float4* __restrict__ sB,
    const ull* __restrict__ sC,
    float lxA0, float lxA1, float lxA2,
    float lxB0, float lxB1, float lxB2,
    ull lx3p, const P2C& C,
    float& fA, float& fB)
{
    const float4 qa = sA[m];
    const float4 qb = sB[m];
    const ull    pw = sC[m];

    // MUFU path: 6 independent EX2s in flight
    const float eA0 = ex2f(qa.y * lxA0);
    const float eB0 = ex2f(qa.y * lxB0);
    const float eA1 = ex2f(qa.w * lxA1);
    const float eB1 = ex2f(qa.w * lxB1);
    const float eA2 = ex2f(qb.y * lxA2);
    const float eB2 = ex2f(qb.y * lxB2);

    // Poly path (var 3): t = pow3 * lg2(x3) for both elems, packed
    float vA, vB;
    exp2_pair(mul2(pw, lx3p), C, vA, vB);

    fA = fmaf(qb.w, vA, fmaf(qa.x, eA0, fmaf(qa.z, eA1, fmaf(qb.x, eA2, qb.z))));
    fB = fmaf(qb.w, vB, fmaf(qa.x, eB0, fmaf(qa.z, eB1, fmaf(qb.x, eB2, qb.z))));
}

__global__ __launch_bounds__(NTHREADS)
void nested_formula_kernel(const float4* __restrict__ x,      // (B, 4) as float4
                           const float*  __restrict__ lam0,   // (125,)
                           const float*  __restrict__ lam1,   // (125,4)
                           const float*  __restrict__ pow1,
                           const float*  __restrict__ lam2,   // (25,4)
                           const float*  __restrict__ pow2,
                           const float*  __restrict__ lam3,   // (5,4)
                           const float*  __restrict__ pow3,
                           const float*  __restrict__ lam4,   // (1,4)
                           const float*  __restrict__ pow4,
                           float* __restrict__ out,           // (B,)
                           int B) {
    __shared__ __align__(16) float4 sA[N1];        // 2000 B
    __shared__ __align__(16) float4 sB[N1];        // 2000 B
    __shared__ __align__(16) ull    sC[N1];        // 1000 B
    __shared__ __align__(16) float2 s2[N2 * NV];   //  800 B
    __shared__ __align__(16) float2 s3[N3 * NV];   //  160 B
    __shared__ __align__(16) float2 s4[NV];        //   32 B

    const int tid = threadIdx.x;
    for (int m = tid; m < N1; m += NTHREADS) {
        sA[m] = make_float4(lam1[4*m+0], pow1[4*m+0], lam1[4*m+1], pow1[4*m+1]);
        sB[m] = make_float4(lam1[4*m+2], pow1[4*m+2], lam0[m],     lam1[4*m+3]);
        const float pw3 = pow1[4*m+3];
        sC[m] = pack2(pw3, pw3);
    }
    for (int i = tid; i < N2 * NV; i += NTHREADS)
        s2[i] = make_float2(lam2[i], pow2[i]);
    if (tid < N3 * NV) s3[tid] = make_float2(lam3[tid], pow3[tid]);
    if (tid < NV)      s4[tid] = make_float2(lam4[tid], pow4[tid]);
    __syncthreads();

    const float4* v2 = (const float4*)s2;

    // Two batch elements per thread, coalesced within the block.
    const int b0 = blockIdx.x * (2 * NTHREADS) + tid;
    const int b1 = b0 + NTHREADS;

    const float4 xA = x[b0];
    const float4 xB = x[b1];
    const float lxA[4] = {lg2f(xA.x), lg2f(xA.y), lg2f(xA.z), lg2f(xA.w)};
    const float lxB[4] = {lg2f(xB.x), lg2f(xB.y), lg2f(xB.z), lg2f(xB.w)};
    const ull lx3p = pack2(lxA[3], lxB[3]);

    // Degree-4 Taylor of 2^f on [-0.5, 0.5]; trunc err ~4e-5 rel (<< 1e-3)
    P2C C;
    C.c4 = pack2(9.6181291e-3f, 9.6181291e-3f);
    C.c3 = pack2(5.5504109e-2f, 5.5504109e-2f);
    C.c2 = pack2(2.4022651e-1f, 2.4022651e-1f);
    C.c1 = pack2(6.9314718e-1f, 6.9314718e-1f);
    C.c0 = pack2(1.0f,          1.0f);

    float acc4A = 0.0f, acc4B = 0.0f;
    #pragma unroll 1
    for (int j = 0; j < 5; ++j) {          // 5 level-3 nodes (root's children)
        float acc3A = 0.0f, acc3B = 0.0f;
        #pragma unroll
        for (int kk = 0; kk < 5; ++kk) {   // 5 level-2 children of node j (unrolled)
            const int k = j * 5 + kk;
            float acc2A, acc2B;
            eval_f1(k * 5 + 4, sA, sB, sC,
                    lxA[0], lxA[1], lxA[2], lxB[0], lxB[1], lxB[2],
                    lx3p, C, acc2A, acc2B);
            const float4 p0 = v2[2 * k];       // (lam_k0,pow_k0,lam_k1,pow_k1)
            const float4 p1 = v2[2 * k + 1];   // (lam_k2,pow_k2,lam_k3,pow_k3)
            #pragma unroll
            for (int mm = 0; mm < 4; ++mm) {
                float fA, fB;
                eval_f1(k * 5 + mm, sA, sB, sC,
                        lxA[0], lxA[1], lxA[2], lxB[0], lxB[1], lxB[2],
                        lx3p, C, fA, fB);
                const float lam = (mm == 0) ? p0.x : (mm == 1) ? p0.z : (mm == 2) ? p1.x : p1.z;
                const float pw  = (mm == 0) ? p0.y : (mm == 1) ? p0.w : (mm == 2) ? p1.y : p1.w;
                acc2A = fmaf(lam * ex2f(pw * lxA[mm]), fA, acc2A);
                acc2B = fmaf(lam * ex2f(pw * lxB[mm]), fB, acc2B);
            }
            if (kk < 4) {
                const float2 lp = s3[j * 4 + kk];
                acc3A = fmaf(lp.x * ex2f(lp.y * lxA[kk]), acc2A, acc3A);
                acc3B = fmaf(lp.x * ex2f(lp.y * lxB[kk]), acc2B, acc3B);
            } else {
                acc3A += acc2A;
                acc3B += acc2B;
            }
        }
        if (j < 4) {
            const float lxjA = (j == 0) ? lxA[0] : (j == 1) ? lxA[1] : (j == 2) ? lxA[2] : lxA[3];
            const float lxjB = (j == 0) ? lxB[0] : (j == 1) ? lxB[1] : (j == 2) ? lxB[2] : lxB[3];
            const float2 lp = s4[j];
            acc4A = fmaf(lp.x * ex2f(lp.y * lxjA), acc3A, acc4A);
            acc4B = fmaf(lp.x * ex2f(lp.y * lxjB), acc3B, acc4B);
        } else {
            acc4A += acc3A;
            acc4B += acc3B;
        }
    }

    out[b0] = acc4A;
    out[b1] = acc4B;
}

extern "C" void kernel_launch(void* const* d_in, const int* in_sizes, int n_in,
                              void* d_out, int out_size) {
    // metadata order: x, lam0, lam1, pow1, lam2, pow2, lam3, pow3, lam4, pow4
    const float4* x    = (const float4*)d_in[0];
    const float*  lam0 = (const float*)d_in[1];
    const float*  lam1 = (const float*)d_in[2];
    const float*  pow1 = (const float*)d_in[3];
    const float*  lam2 = (const float*)d_in[4];
    const float*  pow2 = (const float*)d_in[5];
    const float*  lam3 = (const float*)d_in[6];
    const float*  pow3 = (const float*)d_in[7];
    const float*  lam4 = (const float*)d_in[8];
    const float*  pow4 = (const float*)d_in[9];
    float* out = (float*)d_out;

    const int B = in_sizes[0] / 4;                 // x has B*4 elements
    const int elemsPerBlock = 2 * NTHREADS;        // 128
    const int grid = (B + elemsPerBlock - 1) / elemsPerBlock;
    nested_formula_kernel<<<grid, NTHREADS>>>(x, lam0, lam1, pow1, lam2, pow2,
                                              lam3, pow3, lam4, pow4, out, B);
}